// round 3
// baseline (speedup 1.0000x reference)
#include <cuda_runtime.h>
#include <cstdint>

#define DTW_INF 99999.0f

// Tile configuration: T x T tile per block, P threads, W columns per thread.
constexpr int T = 1024;
constexpr int W = 4;
constexpr int P = 256;          // P * W == T
constexpr int NWARP = P / 32;   // 8

// ---------------------------------------------------------------------------
// Init kernel: write RAW boundary values (row 0 and column 0 of the table).
// ---------------------------------------------------------------------------
__global__ void dtw_init_bounds(float* __restrict__ out, int N, int M)
{
    int Mp1 = M + 1;
    int stride = gridDim.x * blockDim.x;
    int idx = blockIdx.x * blockDim.x + threadIdx.x;
    for (int j = idx; j <= M; j += stride)
        out[j] = (j == 0) ? 0.0f : DTW_INF;
    for (int i = idx + 1; i <= N; i += stride)
        out[(size_t)i * Mp1] = DTW_INF;
}

// ---------------------------------------------------------------------------
// Wavefront kernel: one block computes one T x T tile (RAW values into out).
// Launched once per tile anti-diagonal; halos are read raw from `out`.
// Thread t owns W consecutive columns; at step s it computes local row s - t.
// Neighbor (left-boundary) values travel via shfl within a warp and a
// parity-double-buffered shared ring across warp boundaries.
// ---------------------------------------------------------------------------
__global__ __launch_bounds__(P)
void dtw_diag_kernel(const float* __restrict__ x,
                     const float* __restrict__ y,
                     float* __restrict__ out,
                     int N, int M, int d, int it0)
{
    const int It = it0 + blockIdx.x;
    const int Jt = d - It;
    const int R0 = It * T + 1;     // first table row of this tile
    const int C0 = Jt * T + 1;     // first table col of this tile
    const int Mp1 = M + 1;

    __shared__ float shX[T];          // x values for this tile's rows
    __shared__ float shLeft[T + 1];   // raw left halo: v(R0-1+k, C0-1)
    __shared__ float shRing[2][2][NWARP];  // [parity][last/lastprev][warp]

    const int t = threadIdx.x;
    const int lane = t & 31;
    const int warp = t >> 5;

    // Cooperative halo / input staging.
    for (int k = t; k < T; k += P)
        shX[k] = x[R0 - 1 + k];
    for (int k = t; k <= T; k += P)
        shLeft[k] = out[(size_t)(R0 - 1 + k) * Mp1 + (C0 - 1)];

    // Per-thread column data and top halo.
    const int cbase = C0 + t * W;           // first table col owned by thread
    float yv[W], rowvals[W];
#pragma unroll
    for (int c = 0; c < W; c++) {
        yv[c] = y[cbase - 1 + c];
        rowvals[c] = out[(size_t)(R0 - 1) * Mp1 + cbase + c];  // raw top halo
    }
    float lastv = rowvals[W - 1];   // my last-column value of most recent row
    float lastv_prev = lastv;       // ... of the row before that

    __syncthreads();

    const int NSTEPS = T + P - 1;
    for (int s = 0; s < NSTEPS; ++s) {
        // Values produced by the left-neighbor thread at step s-1 / s-2:
        float n_last  = __shfl_up_sync(0xffffffffu, lastv, 1);
        float n_lastp = __shfl_up_sync(0xffffffffu, lastv_prev, 1);
        if (lane == 0) {
            if (warp == 0) {
                // thread 0: left halo from shared (raw values)
                int li = (s < T) ? s : (T - 1);
                n_last  = shLeft[li + 1];   // v(R0+li,   C0-1)
                n_lastp = shLeft[li];       // v(R0+li-1, C0-1)
            } else {
                int pb = (s + 1) & 1;       // parity of step s-1
                n_last  = shRing[pb][0][warp - 1];
                n_lastp = shRing[pb][1][warp - 1];
            }
        }

        const int li = s - t;
        if (0 <= li && li < T) {
            const float xi = shX[li];
            float diag = n_lastp;   // v(i-1, cbase-1)
            float left = n_last;    // v(i,   cbase-1)
            size_t base = (size_t)(R0 + li) * Mp1 + cbase;
#pragma unroll
            for (int c = 0; c < W; c++) {
                float top = rowvals[c];
                float dd = xi - yv[c];
                float m = fminf(fminf(top, diag), left);
                float v = fmaf(dd, dd, m);
                diag = top;
                left = v;
                rowvals[c] = v;
                out[base + c] = v;   // RAW value; sqrt applied in final pass
            }
            lastv_prev = lastv;
            lastv = left;
        }

        if (lane == 31) {
            int pc = s & 1;
            shRing[pc][0][warp] = lastv;
            shRing[pc][1][warp] = lastv_prev;
        }
        __syncthreads();
    }
}

// ---------------------------------------------------------------------------
// Final pass: elementwise sqrt over the whole table (memory bound).
// ---------------------------------------------------------------------------
__global__ void dtw_sqrt_all(float* __restrict__ out, size_t n)
{
    size_t stride = (size_t)gridDim.x * blockDim.x;
    for (size_t k = (size_t)blockIdx.x * blockDim.x + threadIdx.x; k < n; k += stride)
        out[k] = sqrtf(out[k]);
}

// ---------------------------------------------------------------------------
extern "C" void kernel_launch(void* const* d_in, const int* in_sizes, int n_in,
                              void* d_out, int out_size)
{
    const float* x = (const float*)d_in[0];
    const float* y = (const float*)d_in[1];
    float* out = (float*)d_out;
    const int N = in_sizes[0];
    const int M = in_sizes[1];

    dtw_init_bounds<<<64, 256>>>(out, N, M);

    const int NTr = N / T;
    const int NTc = M / T;
    for (int d = 0; d < NTr + NTc - 1; ++d) {
        int it0 = (d - (NTc - 1) > 0) ? (d - (NTc - 1)) : 0;
        int it1 = (d < NTr - 1) ? d : (NTr - 1);
        int width = it1 - it0 + 1;
        dtw_diag_kernel<<<width, P>>>(x, y, out, N, M, d, it0);
    }

    size_t total = (size_t)(N + 1) * (size_t)(M + 1);
    dtw_sqrt_all<<<1024, 256>>>(out, total);
}

// round 4
// speedup vs baseline: 1.4697x; 1.4697x over previous
#include <cuda_runtime.h>
#include <cstdint>

#define DTW_INF 99999.0f

// Problem size this scratch is dimensioned for (bench: N = M = 6144).
constexpr int MAXN = 6144;
constexpr int MAXM = 6144;

// Diagonal-major scratch: g_buf[(i+j) * (M+1) + j] holds raw (pre-sqrt) DTW value.
__device__ float g_buf[(size_t)(MAXN + MAXM + 1) * (MAXM + 1)];

// Wavefront tile configuration: T x T tile, P threads, 1 column per thread.
constexpr int T = 1024;
constexpr int P = 1024;
constexpr int NW = P / 32;

// ---------------------------------------------------------------------------
// Init: write table boundaries (row 0, col 0) into the diagonal-major scratch.
// ---------------------------------------------------------------------------
__global__ void dtw_init(int N, int M)
{
    const int pitch = M + 1;
    const int stride = gridDim.x * blockDim.x;
    const int idx = blockIdx.x * blockDim.x + threadIdx.x;
    // Row 0: cell (0, j) sits at diagonal d = j, column j.
    for (int j = idx; j <= M; j += stride)
        g_buf[(size_t)j * pitch + j] = (j == 0) ? 0.0f : DTW_INF;
    // Col 0: cell (i, 0) sits at diagonal d = i, column 0.
    for (int i = idx + 1; i <= N; i += stride)
        g_buf[(size_t)i * pitch] = DTW_INF;
}

// ---------------------------------------------------------------------------
// Wavefront kernel: one block = one T x T tile. Thread t owns table column
// C0 + t. At step s it computes local row li = s - t. All cells of a step lie
// on ONE global anti-diagonal d = R0 + C0 + s  =>  stores into g_buf are
// fully coalesced (contiguous in t).
// Neighbor values travel by shfl within a warp and a parity ring in smem
// across warp boundaries; halos are staged from g_buf once per tile.
// ---------------------------------------------------------------------------
__global__ __launch_bounds__(P)
void dtw_wave(const float* __restrict__ x,
              const float* __restrict__ y,
              int N, int M, int d, int it0)
{
    const int It = it0 + blockIdx.x;
    const int Jt = d - It;
    const int R0 = It * T + 1;    // first table row of tile
    const int C0 = Jt * T + 1;    // first table col of tile
    const int pitch = M + 1;

    __shared__ float shX[T];         // x for rows R0..R0+T-1  (x[(R0-1)+k])
    __shared__ float shLeft[T + 1];  // left halo: v(R0-1+k, C0-1)
    __shared__ float ringL[2][NW];   // [parity][warp] : lastv of lane 31
    __shared__ float ringP[2][NW];   // [parity][warp] : lastv_prev of lane 31

    const int t = threadIdx.x;
    const int lane = t & 31;
    const int warp = t >> 5;

    // Stage inputs / halos (bulk, amortized over 2047 steps).
    for (int k = t; k < T; k += P) {
        int gr = R0 - 1 + k;                       // x index for table row gr+1
        shX[k] = (gr < N) ? x[gr] : 0.0f;
    }
    for (int k = t; k <= T; k += P) {
        int gi = R0 - 1 + k;                       // table row of halo entry
        shLeft[k] = (gi <= N)
            ? g_buf[(size_t)(gi + C0 - 1) * pitch + (C0 - 1)]
            : DTW_INF;
    }

    const int jt = C0 + t;                          // this thread's table column
    const bool colok = (jt <= M);
    const float yv = colok ? y[jt - 1] : 0.0f;

    // lastv must start as the top halo v(R0-1, jt): it is both my first "top"
    // and, after one step, the right-neighbor's "diag".
    float lastv = colok ? g_buf[(size_t)(R0 - 1 + jt) * pitch + jt] : DTW_INF;
    float lastv_prev = lastv;

    const int liMax = (N - R0 < T - 1) ? (N - R0) : (T - 1);
    float* p = g_buf + (size_t)(R0 + C0) * pitch + jt;   // step-0 store address

    __syncthreads();

    const int NSTEPS = T + P - 1;
    int li = -t;                                    // li = s - t
#pragma unroll 2
    for (int s = 0; s < NSTEPS; ++s, ++li, p += pitch) {
        // Neighbor thread (column jt-1) values from steps s-1 / s-2.
        float nl = __shfl_up_sync(0xffffffffu, lastv, 1);       // v(li,   jt-1)
        float np = __shfl_up_sync(0xffffffffu, lastv_prev, 1);  // v(li-1, jt-1)
        if (lane == 0) {
            if (warp == 0) {
                int k = li < 0 ? 0 : (li > T - 1 ? T - 1 : li);
                nl = shLeft[k + 1];
                np = shLeft[k];
            } else {
                int pb = (s + 1) & 1;          // parity of step s-1
                nl = ringL[pb][warp - 1];
                np = ringP[pb][warp - 1];
            }
        }

        if (0 <= li && li <= liMax && colok) {
            float xi = shX[li];
            float dd = xi - yv;
            float m = fminf(fminf(lastv, np), nl);   // min(top, diag, left)
            float v = fmaf(dd, dd, m);
            lastv_prev = lastv;
            lastv = v;
            *p = v;                                   // coalesced diag-major store
        }

        if (lane == 31) {
            int pc = s & 1;
            ringL[pc][warp] = lastv;
            ringP[pc][warp] = lastv_prev;
        }
        __syncthreads();
    }
}

// ---------------------------------------------------------------------------
// De-skew + sqrt: out[i][j] = sqrt(g_buf[(i+j)*pitch + j]).
// Parallelogram smem tile: loads coalesced along j in diag space, stores
// coalesced along j in row space. sh[ii+jl][jl] has word-stride 33 across
// jl -> bank-conflict-free.
// ---------------------------------------------------------------------------
constexpr int TR = 128;
constexpr int TC = 32;

__global__ __launch_bounds__(256)
void dtw_deskew(float* __restrict__ out, int N, int M)
{
    __shared__ float sh[TR + TC - 1][TC];

    const int i0 = blockIdx.y * TR;
    const int j0 = blockIdx.x * TC;
    const int pitch = M + 1;
    const int d0 = i0 + j0;

    for (int k = threadIdx.x; k < (TR + TC - 1) * TC; k += 256) {
        int dl = k >> 5;
        int jl = k & 31;
        int dg = d0 + dl;
        int jg = j0 + jl;
        float v = 0.0f;
        if (dg <= N + M && jg <= M)
            v = g_buf[(size_t)dg * pitch + jg];
        sh[dl][jl] = v;
    }
    __syncthreads();

    for (int k = threadIdx.x; k < TR * TC; k += 256) {
        int ii = k >> 5;
        int jl = k & 31;
        int ig = i0 + ii;
        int jg = j0 + jl;
        if (ig <= N && jg <= M)
            out[(size_t)ig * pitch + jg] = sqrtf(sh[ii + jl][jl]);
    }
}

// ---------------------------------------------------------------------------
extern "C" void kernel_launch(void* const* d_in, const int* in_sizes, int n_in,
                              void* d_out, int out_size)
{
    const float* x = (const float*)d_in[0];
    const float* y = (const float*)d_in[1];
    float* out = (float*)d_out;
    const int N = in_sizes[0];
    const int M = in_sizes[1];

    dtw_init<<<64, 256>>>(N, M);

    const int NTr = (N + T - 1) / T;
    const int NTc = (M + T - 1) / T;
    for (int d = 0; d < NTr + NTc - 1; ++d) {
        int it0 = (d - (NTc - 1) > 0) ? (d - (NTc - 1)) : 0;
        int it1 = (d < NTr - 1) ? d : (NTr - 1);
        int width = it1 - it0 + 1;
        dtw_wave<<<width, P>>>(x, y, N, M, d, it0);
    }

    dim3 grid((M + 1 + TC - 1) / TC, (N + 1 + TR - 1) / TR);
    dtw_deskew<<<grid, 256>>>(out, N, M);
}

// round 5
// speedup vs baseline: 1.8797x; 1.2789x over previous
#include <cuda_runtime.h>
#include <cstdint>

#define DTW_INF 99999.0f

// Bench size: N = M = 6144.
constexpr int MAXN = 6144;
constexpr int MAXM = 6144;
constexpr int PITCH = (MAXM + 4 + 3) & ~3;     // 6148, multiple of 4

// Diagonal-major scratch with +3 shift: cell (i,j) lives at
// g_buf[(i+j)*PITCH + j + 3]  ->  thread column groups are float4-aligned.
__device__ float g_buf[(size_t)(MAXN + MAXM + 2) * PITCH + 16];

constexpr int T = 1024;    // tile side (rows = cols = T)
constexpr int P = 256;     // threads per block
constexpr int W = 4;       // columns per thread (P*W == T)
constexpr int NW = P / 32;

__device__ __forceinline__ size_t gidx(int d, int j) {
    return (size_t)d * PITCH + (j + 3);
}

// ---------------------------------------------------------------------------
// Init: table boundaries (row 0, col 0) into diag-major scratch.
// ---------------------------------------------------------------------------
__global__ void dtw_init(int N, int M)
{
    const int stride = gridDim.x * blockDim.x;
    const int idx = blockIdx.x * blockDim.x + threadIdx.x;
    for (int j = idx; j <= M; j += stride)
        g_buf[gidx(j, j)] = (j == 0) ? 0.0f : DTW_INF;
    for (int i = idx + 1; i <= N; i += stride)
        g_buf[gidx(i, 0)] = DTW_INF;
}

// ---------------------------------------------------------------------------
// One anti-diagonal step. cur = register buffer holding diag dl-1,
// oth = buffer holding diag dl-2; new diag dl is written (predicated) into oth.
// DL = dl - W*t (i.e., il for this thread's c=0 column).
// ---------------------------------------------------------------------------
template<int PB, int PC>
__device__ __forceinline__ void dtw_phase(
    float (&cur)[W], float (&oth)[W],
    float (&xw)[W], const float (&yv)[W], const int (&lim)[W],
    int DL, float*& p,
    const float* shX, const float* shLeft,
    float (*ringL)[NW], float (*ringP)[NW],
    int lane, int warp)
{
    // Neighbor thread's (column j0-1) values: diag dl-1 and dl-2.
    float nl = __shfl_up_sync(0xffffffffu, cur[W-1], 1);
    float np = __shfl_up_sync(0xffffffffu, oth[W-1], 1);
    int kk = DL < 0 ? 0 : (DL > T - 1 ? T - 1 : DL);
    if (lane == 0) {
        if (warp == 0) { nl = shLeft[kk + 1]; np = shLeft[kk]; }   // thread 0: left halo
        else           { nl = ringL[PB][warp - 1]; np = ringP[PB][warp - 1]; }
    }

    // x register window: column c needs x at il_c = DL - c.
#pragma unroll
    for (int c = W - 1; c > 0; --c) xw[c] = xw[c - 1];
    xw[0] = shX[kk];

    float dpr = np;   // v(il_c - 1, j_c - 1)  (diag dl-2 of left column)
    float lft = nl;   // v(il_c,     j_c - 1)  (diag dl-1 of left column)
#pragma unroll
    for (int c = 0; c < W; ++c) {
        int il = DL - c;
        float top = cur[c];       // v(il-1, j_c)
        float old = oth[c];       // v(il-2 ... ) -> becomes next column's diag
        float dd = xw[c] - yv[c];
        float m = fminf(fminf(top, lft), dpr);
        float v = fmaf(dd, dd, m);
        if ((il >= 0) && (il <= lim[c])) oth[c] = v;   // predicated in-place write
        dpr = old;
        lft = top;
    }

    // Coalesced store of this thread's 4 cells (all on the SAME diagonal).
    bool aF = (DL >= 0) && (DL <= lim[0]);
    bool aL = (DL - (W - 1) >= 0) && (DL - (W - 1) <= lim[W - 1]);
    if (aF && aL) {
        *reinterpret_cast<float4*>(p) = make_float4(oth[0], oth[1], oth[2], oth[3]);
    } else {
#pragma unroll
        for (int c = 0; c < W; ++c) {
            int il = DL - c;
            if ((il >= 0) && (il <= lim[c])) p[c] = oth[c];
        }
    }

    if (lane == 31) { ringL[PC][warp] = oth[W - 1]; ringP[PC][warp] = cur[W - 1]; }
    p += PITCH;
    __syncthreads();
}

// ---------------------------------------------------------------------------
// Wavefront kernel: one block = one T x T tile; thread t owns columns
// j0..j0+3. Each step computes one tile anti-diagonal (no intra-step chain).
// ---------------------------------------------------------------------------
__global__ __launch_bounds__(P)
void dtw_wave(const float* __restrict__ x, const float* __restrict__ y,
              int N, int M, int d, int it0)
{
    const int It = it0 + blockIdx.x;
    const int Jt = d - It;
    const int R0 = It * T + 1;
    const int C0 = Jt * T + 1;

    __shared__ float shX[T];
    __shared__ float shLeft[T + 1];
    __shared__ float ringL[2][NW];
    __shared__ float ringP[2][NW];

    const int t = threadIdx.x;
    const int lane = t & 31;
    const int warp = t >> 5;

    for (int k = t; k < T; k += P) {
        int gr = R0 - 1 + k;
        shX[k] = (gr < N) ? x[gr] : 0.0f;
    }
    for (int k = t; k <= T; k += P) {
        int gi = R0 - 1 + k;
        shLeft[k] = (gi <= N) ? g_buf[gidx(gi + C0 - 1, C0 - 1)] : DTW_INF;
    }

    const int j0 = C0 + W * t;
    const int liMaxRow = (N - R0 < T - 1) ? (N - R0) : (T - 1);

    float yv[W], pv[W], qv[W], xw[W];
    int lim[W];
#pragma unroll
    for (int c = 0; c < W; ++c) {
        int j = j0 + c;
        bool jok = (j <= M);
        yv[c] = jok ? y[j - 1] : 0.0f;
        float h = jok ? g_buf[gidx(R0 - 1 + j, j)] : DTW_INF;  // top halo
        pv[c] = h; qv[c] = h;
        lim[c] = jok ? liMaxRow : -1;
        xw[c] = 0.0f;
    }

    if (lane == 31) { ringL[1][warp] = pv[W - 1]; ringP[1][warp] = qv[W - 1]; }
    __syncthreads();

    float* p = g_buf + gidx(R0 + C0, j0);
    int dlmt = -W * t;

    // 2T steps (needs 2T-1; last step is fully inactive).
    for (int it = 0; it < T; ++it) {
        dtw_phase<1, 0>(pv, qv, xw, yv, lim, dlmt,     p, shX, shLeft, ringL, ringP, lane, warp);
        dtw_phase<0, 1>(qv, pv, xw, yv, lim, dlmt + 1, p, shX, shLeft, ringL, ringP, lane, warp);
        dlmt += 2;
    }
}

// ---------------------------------------------------------------------------
// De-skew + sqrt: out[i][j] = sqrt(g_buf[gidx(i+j, j)]).
// ---------------------------------------------------------------------------
constexpr int TR = 128;
constexpr int TC = 32;

__global__ __launch_bounds__(256)
void dtw_deskew(float* __restrict__ out, int N, int M)
{
    __shared__ float sh[TR + TC - 1][TC];
    const int i0 = blockIdx.y * TR;
    const int j0 = blockIdx.x * TC;
    const int d0 = i0 + j0;
    const int pitch_out = M + 1;

    for (int k = threadIdx.x; k < (TR + TC - 1) * TC; k += 256) {
        int dl = k >> 5;
        int jl = k & 31;
        int dg = d0 + dl;
        int jg = j0 + jl;
        float v = 0.0f;
        if (dg <= N + M && jg <= M)
            v = g_buf[gidx(dg, jg)];
        sh[dl][jl] = v;
    }
    __syncthreads();

    for (int k = threadIdx.x; k < TR * TC; k += 256) {
        int ii = k >> 5;
        int jl = k & 31;
        int ig = i0 + ii;
        int jg = j0 + jl;
        if (ig <= N && jg <= M)
            out[(size_t)ig * pitch_out + jg] = sqrtf(sh[ii + jl][jl]);
    }
}

// ---------------------------------------------------------------------------
extern "C" void kernel_launch(void* const* d_in, const int* in_sizes, int n_in,
                              void* d_out, int out_size)
{
    const float* x = (const float*)d_in[0];
    const float* y = (const float*)d_in[1];
    float* out = (float*)d_out;
    const int N = in_sizes[0];
    const int M = in_sizes[1];

    dtw_init<<<64, 256>>>(N, M);

    const int NTr = (N + T - 1) / T;
    const int NTc = (M + T - 1) / T;
    for (int d = 0; d < NTr + NTc - 1; ++d) {
        int it0 = (d - (NTc - 1) > 0) ? (d - (NTc - 1)) : 0;
        int it1 = (d < NTr - 1) ? d : (NTr - 1);
        int width = it1 - it0 + 1;
        dtw_wave<<<width, P>>>(x, y, N, M, d, it0);
    }

    dim3 grid((M + 1 + TC - 1) / TC, (N + 1 + TR - 1) / TR);
    dtw_deskew<<<grid, 256>>>(out, N, M);
}